// round 13
// baseline (speedup 1.0000x reference)
#include <cuda_runtime.h>
#include <cuda_fp16.h>

#define N_NODES 200000
#define N_EDGES 6400000
#define D_IN    100
#define D_H1    65
#define H1H     72      // fp16 row pad: 9 x uint4 (8 halves each) = 144B
#define D_H2    64      // fp16 row: 8 x uint4 = 128B

#define SCAN_B  1024
#define SCAN_NB ((N_NODES + SCAN_B - 1) / SCAN_B)   // 196

// ---------------- scratch (device globals; no allocation allowed) -----------
__device__ uint4  g_h1h [(N_NODES * H1H) / 8];   // 28.8 MB  fp16 h1*dinv
__device__ uint4  g_a1h [(N_NODES * H1H) / 8];   // 28.8 MB  fp16 relu(agg1+b1)
__device__ uint4  g_h2h [(N_NODES * D_H2) / 8];  // 25.6 MB  fp16 h2*dinv
__device__ float  g_dinv[N_NODES];
__device__ int    g_deg [N_NODES];
__device__ int    g_rowptr[N_NODES + 1];
__device__ int    g_cursor[N_NODES];
__device__ __align__(16) int g_esrc[N_EDGES];    // CSR: src ids grouped by dst
__device__ int    g_bsum[SCAN_NB];               // per-block scan totals

// ---------------- degree -----------------------------------------------------
__global__ void k_deg_zero() {
    int i = blockIdx.x * blockDim.x + threadIdx.x;
    if (i < N_NODES) g_deg[i] = 0;
}

__global__ void k_deg_count(const int* __restrict__ ei) {
    int e = blockIdx.x * blockDim.x + threadIdx.x;
    if (e < N_EDGES) atomicAdd(&g_deg[ei[N_EDGES + e]], 1);   // dst = ei[1]
}

// ---------------- scan pass 1 (+ fused dinv) ---------------------------------
__global__ __launch_bounds__(SCAN_B) void k_scan1() {
    __shared__ int wsum[32];
    int t = threadIdx.x, lane = t & 31, wid = t >> 5;
    int idx = blockIdx.x * SCAN_B + t;
    int v = (idx < N_NODES) ? g_deg[idx] : 0;
    int x = v;
#pragma unroll
    for (int off = 1; off < 32; off <<= 1) {
        int n = __shfl_up_sync(0xffffffffu, x, off);
        if (lane >= off) x += n;
    }
    if (lane == 31) wsum[wid] = x;
    __syncthreads();
    if (wid == 0) {
        int w = wsum[lane];
#pragma unroll
        for (int off = 1; off < 32; off <<= 1) {
            int n = __shfl_up_sync(0xffffffffu, w, off);
            if (lane >= off) w += n;
        }
        wsum[lane] = w;
    }
    __syncthreads();
    int warpoff = (wid > 0) ? wsum[wid - 1] : 0;
    int excl = x - v + warpoff;
    if (idx < N_NODES) {
        g_rowptr[idx] = excl;
        g_dinv[idx]   = rsqrtf((float)(v + 1));   // +1 self loop
    }
    if (t == SCAN_B - 1) g_bsum[blockIdx.x] = warpoff + x;
}

// ---------------- scan pass 2 ------------------------------------------------
__global__ __launch_bounds__(256) void k_scan2() {
    __shared__ int wsum[8];
    int t = threadIdx.x, lane = t & 31, wid = t >> 5;
    int v = (t < SCAN_NB) ? g_bsum[t] : 0;
    int x = v;
#pragma unroll
    for (int off = 1; off < 32; off <<= 1) {
        int n = __shfl_up_sync(0xffffffffu, x, off);
        if (lane >= off) x += n;
    }
    if (lane == 31) wsum[wid] = x;
    __syncthreads();
    if (wid == 0 && lane < 8) {
        int w = wsum[lane];
#pragma unroll
        for (int off = 1; off < 8; off <<= 1) {
            int n = __shfl_up_sync(0xffu, w, off);
            if (lane >= off) w += n;
        }
        wsum[lane] = w;
    }
    __syncthreads();
    int warpoff = (wid > 0) ? wsum[wid - 1] : 0;
    int excl = x - v + warpoff;
    if (t < SCAN_NB) g_bsum[t] = excl;
    if (t == SCAN_NB - 1) g_rowptr[N_NODES] = excl + v;
}

// ---------------- scan pass 3 ------------------------------------------------
__global__ __launch_bounds__(SCAN_B) void k_scan3() {
    int idx = blockIdx.x * SCAN_B + threadIdx.x;
    if (idx < N_NODES) {
        int r = g_rowptr[idx] + g_bsum[blockIdx.x];
        g_rowptr[idx] = r;
        g_cursor[idx] = r;
    }
}

// -------- GEMM1 (tensor core) + fused CSR scatter ----------------------------
#define XS_STRIDE 57    // half2 words per row (56 data + 1 pad, odd stride)
__global__ __launch_bounds__(256) void k_gemm1(const float* __restrict__ x,
                                               const float* __restrict__ W1,
                                               const int* __restrict__ ei) {
    __shared__ __half2 Xs[128 * XS_STRIDE];  // 29.2 KB
    __shared__ __half2 Wsm[56 * 72];         // 16.1 KB  (k-pair, n)
    int t = threadIdx.x;
    int rbase = blockIdx.x * 128;

    // W staging: (kp, n) incremental (256 = 3*72+40)
    {
        int kp = t / 72, n = t - kp * 72;
        for (int idx = t; idx < 56 * 72; idx += 256) {
            int k0 = 2 * kp;
            float lo = (k0 < D_IN && n < D_H1) ? W1[k0 * D_H1 + n] : 0.0f;
            float hi = (k0 + 1 < D_IN && n < D_H1) ? W1[(k0 + 1) * D_H1 + n] : 0.0f;
            Wsm[kp * 72 + n] = __floats2half2_rn(lo, hi);
            kp += 3; n += 40;
            if (n >= 72) { n -= 72; kp += 1; }
        }
    }

    // X staging: (rr, kp) incremental (256 = 4*56+32)
    {
        int rr = t / 56, kp = t - rr * 56;
        for (int idx = t; idx < 128 * 56; idx += 256) {
            int row = rbase + rr;
            __half2 v = __floats2half2_rn(0.0f, 0.0f);
            if (row < N_NODES && kp < 50) {
                float2 f2 = *(const float2*)(x + (size_t)row * D_IN + 2 * kp);
                v = __floats2half2_rn(f2.x, f2.y);
            }
            Xs[rr * XS_STRIDE + kp] = v;
            rr += 4; kp += 32;
            if (kp >= 56) { kp -= 56; rr += 1; }
        }
    }
    __syncthreads();

    int w    = t >> 5;
    int lane = t & 31;
    int g    = lane >> 2;
    int tig  = lane & 3;
    int m0   = w * 16;

    float acc[9][4];
#pragma unroll
    for (int nt = 0; nt < 9; nt++)
#pragma unroll
        for (int j = 0; j < 4; j++) acc[nt][j] = 0.0f;

    const unsigned* XsU = (const unsigned*)Xs;
    const unsigned* WsU = (const unsigned*)Wsm;

#pragma unroll
    for (int ks = 0; ks < 7; ks++) {
        int kb = ks * 8;
        unsigned a0 = XsU[(m0 + g)     * XS_STRIDE + kb + tig];
        unsigned a1 = XsU[(m0 + g + 8) * XS_STRIDE + kb + tig];
        unsigned a2 = XsU[(m0 + g)     * XS_STRIDE + kb + 4 + tig];
        unsigned a3 = XsU[(m0 + g + 8) * XS_STRIDE + kb + 4 + tig];
#pragma unroll
        for (int nt = 0; nt < 9; nt++) {
            unsigned b0 = WsU[(kb + tig)     * 72 + nt * 8 + g];
            unsigned b1 = WsU[(kb + 4 + tig) * 72 + nt * 8 + g];
            asm volatile(
                "mma.sync.aligned.m16n8k16.row.col.f32.f16.f16.f32 "
                "{%0,%1,%2,%3}, {%4,%5,%6,%7}, {%8,%9}, {%0,%1,%2,%3};"
                : "+f"(acc[nt][0]), "+f"(acc[nt][1]),
                  "+f"(acc[nt][2]), "+f"(acc[nt][3])
                : "r"(a0), "r"(a1), "r"(a2), "r"(a3), "r"(b0), "r"(b1));
        }
    }

    __half2* h2out = (__half2*)g_h1h;          // row stride 36 half2
    int row0 = rbase + m0 + g;
    int row1 = row0 + 8;
    float d0 = (row0 < N_NODES) ? g_dinv[row0] : 0.0f;
    float d1 = (row1 < N_NODES) ? g_dinv[row1] : 0.0f;
#pragma unroll
    for (int nt = 0; nt < 9; nt++) {
        int cw = nt * 4 + tig;
        if (row0 < N_NODES)
            h2out[(unsigned)row0 * 36 + cw] =
                __floats2half2_rn(acc[nt][0] * d0, acc[nt][1] * d0);
        if (row1 < N_NODES)
            h2out[(unsigned)row1 * 36 + cw] =
                __floats2half2_rn(acc[nt][2] * d1, acc[nt][3] * d1);
    }

    // -------- fused CSR scatter: this block's 4096-edge slice ---------------
    {
        int base = blockIdx.x * 4096;
        int lim  = base + 4096;
        if (lim > N_EDGES) lim = N_EDGES;
        for (int e = base + t; e < lim; e += 256) {
            int s = __ldg(&ei[e]);
            int d = __ldg(&ei[N_EDGES + e]);
            int pos = atomicAdd(&g_cursor[d], 1);
            g_esrc[pos] = s;
        }
    }
}

// ---------------- fp16 chunk accumulate --------------------------------------
__device__ __forceinline__ void acc_chunk(float* a, uint4 q) {
    const __half2* hp = (const __half2*)&q;
#pragma unroll
    for (int j = 0; j < 4; j++) {
        float2 f = __half22float2(hp[j]);
        a[2 * j]     += f.x;
        a[2 * j + 1] += f.y;
    }
}

// ------ agg1: a1h[i] = fp16( relu( dinv[i]*(hs1[i] + sum hs1[src]) + b1 ) ) --
// int4 edge loads + 8-deep gather pipeline.
__global__ __launch_bounds__(288) void k_agg1(const float* __restrict__ b1) {
    int t  = threadIdx.x;
    int ln = t / 9;
    int c  = t - ln * 9;
    int i  = blockIdx.x * 32 + ln;
    if (i >= N_NODES) return;

    const uint4* hs = (const uint4*)g_h1h;      // N x 9 chunks
    int beg = __ldg(&g_rowptr[i]);
    int end = __ldg(&g_rowptr[i + 1]);

    float a[8] = {0, 0, 0, 0, 0, 0, 0, 0};
    acc_chunk(a, __ldg(&hs[(unsigned)i * 9 + c]));      // self loop

    int k = beg;
    for (; k < end && (k & 3); k++)                     // head to 16B align
        acc_chunk(a, __ldg(&hs[(unsigned)__ldg(&g_esrc[k]) * 9 + c]));

    for (; k + 7 < end; k += 8) {
        int4 sa = __ldg((const int4*)(g_esrc + k));
        int4 sb = __ldg((const int4*)(g_esrc + k + 4));
        uint4 q0 = __ldg(&hs[(unsigned)sa.x * 9 + c]);
        uint4 q1 = __ldg(&hs[(unsigned)sa.y * 9 + c]);
        uint4 q2 = __ldg(&hs[(unsigned)sa.z * 9 + c]);
        uint4 q3 = __ldg(&hs[(unsigned)sa.w * 9 + c]);
        uint4 q4 = __ldg(&hs[(unsigned)sb.x * 9 + c]);
        uint4 q5 = __ldg(&hs[(unsigned)sb.y * 9 + c]);
        uint4 q6 = __ldg(&hs[(unsigned)sb.z * 9 + c]);
        uint4 q7 = __ldg(&hs[(unsigned)sb.w * 9 + c]);
        acc_chunk(a, q0); acc_chunk(a, q1); acc_chunk(a, q2); acc_chunk(a, q3);
        acc_chunk(a, q4); acc_chunk(a, q5); acc_chunk(a, q6); acc_chunk(a, q7);
    }
    for (; k + 3 < end; k += 4) {
        int4 sa = __ldg((const int4*)(g_esrc + k));
        uint4 q0 = __ldg(&hs[(unsigned)sa.x * 9 + c]);
        uint4 q1 = __ldg(&hs[(unsigned)sa.y * 9 + c]);
        uint4 q2 = __ldg(&hs[(unsigned)sa.z * 9 + c]);
        uint4 q3 = __ldg(&hs[(unsigned)sa.w * 9 + c]);
        acc_chunk(a, q0); acc_chunk(a, q1); acc_chunk(a, q2); acc_chunk(a, q3);
    }
    for (; k < end; k++)
        acc_chunk(a, __ldg(&hs[(unsigned)__ldg(&g_esrc[k]) * 9 + c]));

    float d = __ldg(&g_dinv[i]);
    uint4 u;
    __half2* hp = (__half2*)&u;
#pragma unroll
    for (int j = 0; j < 4; j++) {
        int col = 8 * c + 2 * j;
        float bv0 = (col     < D_H1) ? __ldg(b1 + col)     : 0.0f;
        float bv1 = (col + 1 < D_H1) ? __ldg(b1 + col + 1) : 0.0f;
        float v0 = fmaxf(d * a[2 * j]     + bv0, 0.0f);
        float v1 = fmaxf(d * a[2 * j + 1] + bv1, 0.0f);
        hp[j] = __floats2half2_rn(v0, v1);
    }
    g_a1h[(unsigned)i * 9 + c] = u;
}

// ---------------- GEMM2 (tensor core): hs2 = (a1h @ W2) * dinv -> fp16 ------
#define XS2_STRIDE 41   // half2 words per row (40 data + 1 pad, odd stride)
__global__ __launch_bounds__(256) void k_gemm2(const float* __restrict__ W2) {
    __shared__ __half2 Xs[128 * XS2_STRIDE]; // 21.0 KB
    __shared__ __half2 Wsm[40 * 72];         // 11.5 KB
    int t = threadIdx.x;
    int rbase = blockIdx.x * 128;

    // W staging incremental (256 = 3*72+40)
    {
        int kp = t / 72, n = t - kp * 72;
        for (int idx = t; idx < 40 * 72; idx += 256) {
            int k0 = 2 * kp;
            float lo = (k0 < D_H1 && n < D_H2) ? W2[k0 * D_H2 + n] : 0.0f;
            float hi = (k0 + 1 < D_H1 && n < D_H2) ? W2[(k0 + 1) * D_H2 + n] : 0.0f;
            Wsm[kp * 72 + n] = __floats2half2_rn(lo, hi);
            kp += 3; n += 40;
            if (n >= 72) { n -= 72; kp += 1; }
        }
    }

    // X staging incremental (256 = 6*40+16)
    {
        const __half2* a1 = (const __half2*)g_a1h;   // row stride 36 half2
        int rr = t / 40, kp = t - rr * 40;
        for (int idx = t; idx < 128 * 40; idx += 256) {
            int row = rbase + rr;
            __half2 v = __floats2half2_rn(0.0f, 0.0f);
            if (row < N_NODES && kp < 36) v = a1[(unsigned)row * 36 + kp];
            Xs[rr * XS2_STRIDE + kp] = v;
            rr += 6; kp += 16;
            if (kp >= 40) { kp -= 40; rr += 1; }
        }
    }
    __syncthreads();

    int w    = t >> 5;
    int lane = t & 31;
    int g    = lane >> 2;
    int tig  = lane & 3;
    int m0   = w * 16;

    float acc[8][4];
#pragma unroll
    for (int nt = 0; nt < 8; nt++)
#pragma unroll
        for (int j = 0; j < 4; j++) acc[nt][j] = 0.0f;

    const unsigned* XsU = (const unsigned*)Xs;
    const unsigned* WsU = (const unsigned*)Wsm;

#pragma unroll
    for (int ks = 0; ks < 5; ks++) {
        int kb = ks * 8;
        unsigned a0 = XsU[(m0 + g)     * XS2_STRIDE + kb + tig];
        unsigned a1r= XsU[(m0 + g + 8) * XS2_STRIDE + kb + tig];
        unsigned a2 = XsU[(m0 + g)     * XS2_STRIDE + kb + 4 + tig];
        unsigned a3 = XsU[(m0 + g + 8) * XS2_STRIDE + kb + 4 + tig];
#pragma unroll
        for (int nt = 0; nt < 8; nt++) {
            unsigned b0 = WsU[(kb + tig)     * 72 + nt * 8 + g];
            unsigned b1 = WsU[(kb + 4 + tig) * 72 + nt * 8 + g];
            asm volatile(
                "mma.sync.aligned.m16n8k16.row.col.f32.f16.f16.f32 "
                "{%0,%1,%2,%3}, {%4,%5,%6,%7}, {%8,%9}, {%0,%1,%2,%3};"
                : "+f"(acc[nt][0]), "+f"(acc[nt][1]),
                  "+f"(acc[nt][2]), "+f"(acc[nt][3])
                : "r"(a0), "r"(a1r), "r"(a2), "r"(a3), "r"(b0), "r"(b1));
        }
    }

    __half2* h2out = (__half2*)g_h2h;          // row stride 32 half2
    int row0 = rbase + m0 + g;
    int row1 = row0 + 8;
    float d0 = (row0 < N_NODES) ? g_dinv[row0] : 0.0f;
    float d1 = (row1 < N_NODES) ? g_dinv[row1] : 0.0f;
#pragma unroll
    for (int nt = 0; nt < 8; nt++) {
        int cw = nt * 4 + tig;
        if (row0 < N_NODES)
            h2out[(unsigned)row0 * 32 + cw] =
                __floats2half2_rn(acc[nt][0] * d0, acc[nt][1] * d0);
        if (row1 < N_NODES)
            h2out[(unsigned)row1 * 32 + cw] =
                __floats2half2_rn(acc[nt][2] * d1, acc[nt][3] * d1);
    }
}

// ------- agg2 + output fused: out[i]=relu(sum_c relu(agg2_c+b2)*Wout + bout) -
// int4 edge loads + 8-deep gather pipeline.
__global__ __launch_bounds__(256) void k_agg2out(const float* __restrict__ b2,
                                                 const float* __restrict__ Wout,
                                                 const float* __restrict__ bout,
                                                 float* __restrict__ out) {
    int t  = threadIdx.x;
    int ln = t >> 3;
    int c  = t & 7;
    int i  = blockIdx.x * 32 + ln;
    if (i >= N_NODES) return;

    const uint4* hs = (const uint4*)g_h2h;      // N x 8 chunks
    int beg = __ldg(&g_rowptr[i]);
    int end = __ldg(&g_rowptr[i + 1]);

    float a[8] = {0, 0, 0, 0, 0, 0, 0, 0};
    acc_chunk(a, __ldg(&hs[(unsigned)i * 8 + c]));      // self loop

    int k = beg;
    for (; k < end && (k & 3); k++)                     // head to 16B align
        acc_chunk(a, __ldg(&hs[(unsigned)__ldg(&g_esrc[k]) * 8 + c]));

    for (; k + 7 < end; k += 8) {
        int4 sa = __ldg((const int4*)(g_esrc + k));
        int4 sb = __ldg((const int4*)(g_esrc + k + 4));
        uint4 q0 = __ldg(&hs[(unsigned)sa.x * 8 + c]);
        uint4 q1 = __ldg(&hs[(unsigned)sa.y * 8 + c]);
        uint4 q2 = __ldg(&hs[(unsigned)sa.z * 8 + c]);
        uint4 q3 = __ldg(&hs[(unsigned)sa.w * 8 + c]);
        uint4 q4 = __ldg(&hs[(unsigned)sb.x * 8 + c]);
        uint4 q5 = __ldg(&hs[(unsigned)sb.y * 8 + c]);
        uint4 q6 = __ldg(&hs[(unsigned)sb.z * 8 + c]);
        uint4 q7 = __ldg(&hs[(unsigned)sb.w * 8 + c]);
        acc_chunk(a, q0); acc_chunk(a, q1); acc_chunk(a, q2); acc_chunk(a, q3);
        acc_chunk(a, q4); acc_chunk(a, q5); acc_chunk(a, q6); acc_chunk(a, q7);
    }
    for (; k + 3 < end; k += 4) {
        int4 sa = __ldg((const int4*)(g_esrc + k));
        uint4 q0 = __ldg(&hs[(unsigned)sa.x * 8 + c]);
        uint4 q1 = __ldg(&hs[(unsigned)sa.y * 8 + c]);
        uint4 q2 = __ldg(&hs[(unsigned)sa.z * 8 + c]);
        uint4 q3 = __ldg(&hs[(unsigned)sa.w * 8 + c]);
        acc_chunk(a, q0); acc_chunk(a, q1); acc_chunk(a, q2); acc_chunk(a, q3);
    }
    for (; k < end; k++)
        acc_chunk(a, __ldg(&hs[(unsigned)__ldg(&g_esrc[k]) * 8 + c]));

    float d = __ldg(&g_dinv[i]);
    float4 b2a = __ldg((const float4*)b2 + c * 2);
    float4 b2b = __ldg((const float4*)b2 + c * 2 + 1);
    float4 woa = __ldg((const float4*)Wout + c * 2);
    float4 wob = __ldg((const float4*)Wout + c * 2 + 1);

    float s = fmaxf(d * a[0] + b2a.x, 0.0f) * woa.x
            + fmaxf(d * a[1] + b2a.y, 0.0f) * woa.y
            + fmaxf(d * a[2] + b2a.z, 0.0f) * woa.z
            + fmaxf(d * a[3] + b2a.w, 0.0f) * woa.w
            + fmaxf(d * a[4] + b2b.x, 0.0f) * wob.x
            + fmaxf(d * a[5] + b2b.y, 0.0f) * wob.y
            + fmaxf(d * a[6] + b2b.z, 0.0f) * wob.z
            + fmaxf(d * a[7] + b2b.w, 0.0f) * wob.w;

    s += __shfl_xor_sync(0xffffffffu, s, 1);
    s += __shfl_xor_sync(0xffffffffu, s, 2);
    s += __shfl_xor_sync(0xffffffffu, s, 4);
    if (c == 0) out[i] = fmaxf(s + __ldg(bout), 0.0f);
}

// ---------------- launch ----------------------------------------------------
extern "C" void kernel_launch(void* const* d_in, const int* in_sizes, int n_in,
                              void* d_out, int out_size) {
    const float* x    = (const float*)d_in[0];
    const int*   ei   = (const int*)  d_in[1];
    const float* W1   = (const float*)d_in[2];
    const float* b1   = (const float*)d_in[3];
    const float* W2   = (const float*)d_in[4];
    const float* b2   = (const float*)d_in[5];
    const float* Wout = (const float*)d_in[6];
    const float* bout = (const float*)d_in[7];
    float* out = (float*)d_out;

    const int NB_N = (N_NODES + 255) / 256;
    const int NB_E = (N_EDGES + 255) / 256;
    const int NB_G = (N_NODES + 127) / 128;   // 1563 blocks, 128 rows each
    const int NB_A = (N_NODES + 31) / 32;     // 6250

    k_deg_zero <<<NB_N, 256>>>();
    k_deg_count<<<NB_E, 256>>>(ei);
    k_scan1    <<<SCAN_NB, SCAN_B>>>();       // also computes dinv
    k_scan2    <<<1, 256>>>();
    k_scan3    <<<SCAN_NB, SCAN_B>>>();
    k_gemm1    <<<NB_G, 256>>>(x, W1, ei);    // MMA + fused CSR scatter
    k_agg1     <<<NB_A, 288>>>(b1);
    k_gemm2    <<<NB_G, 256>>>(W2);
    k_agg2out  <<<NB_A, 256>>>(b2, Wout, bout, out);
}

// round 14
// speedup vs baseline: 1.0451x; 1.0451x over previous
#include <cuda_runtime.h>
#include <cuda_fp16.h>

#define N_NODES 200000
#define N_EDGES 6400000
#define D_IN    100
#define D_H1    65
#define H1H     72      // fp16 row pad: 9 x uint4 (8 halves each) = 144B
#define D_H2    64      // fp16 row: 8 x uint4 = 128B

#define SCAN_B  1024
#define SCAN_NB ((N_NODES + SCAN_B - 1) / SCAN_B)   // 196

// ---------------- scratch (device globals; no allocation allowed) -----------
__device__ uint4  g_h1h [(N_NODES * H1H) / 8];   // 28.8 MB  fp16 h1*dinv
__device__ uint4  g_a1h [(N_NODES * H1H) / 8];   // 28.8 MB  fp16 relu(agg1+b1)
__device__ uint4  g_h2h [(N_NODES * D_H2) / 8];  // 25.6 MB  fp16 h2*dinv
__device__ float  g_dinv[N_NODES];
__device__ int    g_deg [N_NODES];
__device__ int    g_rowptr[N_NODES + 1];
__device__ int    g_cursor[N_NODES];
__device__ int    g_esrc[N_EDGES];               // CSR: src ids grouped by dst
__device__ int    g_bsum[SCAN_NB];               // per-block scan totals

// ---------------- degree -----------------------------------------------------
__global__ void k_deg_zero() {
    int i = blockIdx.x * blockDim.x + threadIdx.x;
    if (i < N_NODES) g_deg[i] = 0;
}

// 4 edges per thread via int4 (N_EDGES % 4 == 0, ei 16B-aligned)
__global__ void k_deg_count(const int* __restrict__ ei) {
    int q = blockIdx.x * blockDim.x + threadIdx.x;
    if (q < N_EDGES / 4) {
        int4 d4 = __ldg((const int4*)(ei + N_EDGES) + q);
        atomicAdd(&g_deg[d4.x], 1);
        atomicAdd(&g_deg[d4.y], 1);
        atomicAdd(&g_deg[d4.z], 1);
        atomicAdd(&g_deg[d4.w], 1);
    }
}

// ---------------- scan pass 1 (+ fused dinv) ---------------------------------
__global__ __launch_bounds__(SCAN_B) void k_scan1() {
    __shared__ int wsum[32];
    int t = threadIdx.x, lane = t & 31, wid = t >> 5;
    int idx = blockIdx.x * SCAN_B + t;
    int v = (idx < N_NODES) ? g_deg[idx] : 0;
    int x = v;
#pragma unroll
    for (int off = 1; off < 32; off <<= 1) {
        int n = __shfl_up_sync(0xffffffffu, x, off);
        if (lane >= off) x += n;
    }
    if (lane == 31) wsum[wid] = x;
    __syncthreads();
    if (wid == 0) {
        int w = wsum[lane];
#pragma unroll
        for (int off = 1; off < 32; off <<= 1) {
            int n = __shfl_up_sync(0xffffffffu, w, off);
            if (lane >= off) w += n;
        }
        wsum[lane] = w;
    }
    __syncthreads();
    int warpoff = (wid > 0) ? wsum[wid - 1] : 0;
    int excl = x - v + warpoff;
    if (idx < N_NODES) {
        g_rowptr[idx] = excl;
        g_dinv[idx]   = rsqrtf((float)(v + 1));   // +1 self loop
    }
    if (t == SCAN_B - 1) g_bsum[blockIdx.x] = warpoff + x;
}

// ---------------- scan pass 2 ------------------------------------------------
__global__ __launch_bounds__(256) void k_scan2() {
    __shared__ int wsum[8];
    int t = threadIdx.x, lane = t & 31, wid = t >> 5;
    int v = (t < SCAN_NB) ? g_bsum[t] : 0;
    int x = v;
#pragma unroll
    for (int off = 1; off < 32; off <<= 1) {
        int n = __shfl_up_sync(0xffffffffu, x, off);
        if (lane >= off) x += n;
    }
    if (lane == 31) wsum[wid] = x;
    __syncthreads();
    if (wid == 0 && lane < 8) {
        int w = wsum[lane];
#pragma unroll
        for (int off = 1; off < 8; off <<= 1) {
            int n = __shfl_up_sync(0xffu, w, off);
            if (lane >= off) w += n;
        }
        wsum[lane] = w;
    }
    __syncthreads();
    int warpoff = (wid > 0) ? wsum[wid - 1] : 0;
    int excl = x - v + warpoff;
    if (t < SCAN_NB) g_bsum[t] = excl;
    if (t == SCAN_NB - 1) g_rowptr[N_NODES] = excl + v;
}

// ---------------- scan pass 3 ------------------------------------------------
__global__ __launch_bounds__(SCAN_B) void k_scan3() {
    int idx = blockIdx.x * SCAN_B + threadIdx.x;
    if (idx < N_NODES) {
        int r = g_rowptr[idx] + g_bsum[blockIdx.x];
        g_rowptr[idx] = r;
        g_cursor[idx] = r;
    }
}

// -------- GEMM1 (tensor core) + fused CSR scatter ----------------------------
#define XS_STRIDE 57    // half2 words per row (56 data + 1 pad, odd stride)
__global__ __launch_bounds__(256) void k_gemm1(const float* __restrict__ x,
                                               const float* __restrict__ W1,
                                               const int* __restrict__ ei) {
    __shared__ __half2 Xs[128 * XS_STRIDE];  // 29.2 KB
    __shared__ __half2 Wsm[56 * 72];         // 16.1 KB  (k-pair, n)
    int t = threadIdx.x;
    int rbase = blockIdx.x * 128;

    // W staging: (kp, n) incremental (256 = 3*72+40)
    {
        int kp = t / 72, n = t - kp * 72;
        for (int idx = t; idx < 56 * 72; idx += 256) {
            int k0 = 2 * kp;
            float lo = (k0 < D_IN && n < D_H1) ? W1[k0 * D_H1 + n] : 0.0f;
            float hi = (k0 + 1 < D_IN && n < D_H1) ? W1[(k0 + 1) * D_H1 + n] : 0.0f;
            Wsm[kp * 72 + n] = __floats2half2_rn(lo, hi);
            kp += 3; n += 40;
            if (n >= 72) { n -= 72; kp += 1; }
        }
    }

    // X staging: (rr, kp) incremental (256 = 4*56+32)
    {
        int rr = t / 56, kp = t - rr * 56;
        for (int idx = t; idx < 128 * 56; idx += 256) {
            int row = rbase + rr;
            __half2 v = __floats2half2_rn(0.0f, 0.0f);
            if (row < N_NODES && kp < 50) {
                float2 f2 = *(const float2*)(x + (size_t)row * D_IN + 2 * kp);
                v = __floats2half2_rn(f2.x, f2.y);
            }
            Xs[rr * XS_STRIDE + kp] = v;
            rr += 4; kp += 32;
            if (kp >= 56) { kp -= 56; rr += 1; }
        }
    }
    __syncthreads();

    int w    = t >> 5;
    int lane = t & 31;
    int g    = lane >> 2;
    int tig  = lane & 3;
    int m0   = w * 16;

    float acc[9][4];
#pragma unroll
    for (int nt = 0; nt < 9; nt++)
#pragma unroll
        for (int j = 0; j < 4; j++) acc[nt][j] = 0.0f;

    const unsigned* XsU = (const unsigned*)Xs;
    const unsigned* WsU = (const unsigned*)Wsm;

#pragma unroll
    for (int ks = 0; ks < 7; ks++) {
        int kb = ks * 8;
        unsigned a0 = XsU[(m0 + g)     * XS_STRIDE + kb + tig];
        unsigned a1 = XsU[(m0 + g + 8) * XS_STRIDE + kb + tig];
        unsigned a2 = XsU[(m0 + g)     * XS_STRIDE + kb + 4 + tig];
        unsigned a3 = XsU[(m0 + g + 8) * XS_STRIDE + kb + 4 + tig];
#pragma unroll
        for (int nt = 0; nt < 9; nt++) {
            unsigned b0 = WsU[(kb + tig)     * 72 + nt * 8 + g];
            unsigned b1 = WsU[(kb + 4 + tig) * 72 + nt * 8 + g];
            asm volatile(
                "mma.sync.aligned.m16n8k16.row.col.f32.f16.f16.f32 "
                "{%0,%1,%2,%3}, {%4,%5,%6,%7}, {%8,%9}, {%0,%1,%2,%3};"
                : "+f"(acc[nt][0]), "+f"(acc[nt][1]),
                  "+f"(acc[nt][2]), "+f"(acc[nt][3])
                : "r"(a0), "r"(a1), "r"(a2), "r"(a3), "r"(b0), "r"(b1));
        }
    }

    __half2* h2out = (__half2*)g_h1h;          // row stride 36 half2
    int row0 = rbase + m0 + g;
    int row1 = row0 + 8;
    float d0 = (row0 < N_NODES) ? g_dinv[row0] : 0.0f;
    float d1 = (row1 < N_NODES) ? g_dinv[row1] : 0.0f;
#pragma unroll
    for (int nt = 0; nt < 9; nt++) {
        int cw = nt * 4 + tig;
        if (row0 < N_NODES)
            h2out[(unsigned)row0 * 36 + cw] =
                __floats2half2_rn(acc[nt][0] * d0, acc[nt][1] * d0);
        if (row1 < N_NODES)
            h2out[(unsigned)row1 * 36 + cw] =
                __floats2half2_rn(acc[nt][2] * d1, acc[nt][3] * d1);
    }

    // ---- fused CSR scatter: this block's 4096-edge slice (int4 reads) ------
    {
        int qbase = blockIdx.x * 1024;           // 1024 int4 groups = 4096 edges
        int qlim  = qbase + 1024;
        int qmax  = N_EDGES / 4;
        if (qlim > qmax) qlim = qmax;
        for (int q = qbase + t; q < qlim; q += 256) {
            int4 s4 = __ldg((const int4*)ei + q);
            int4 d4 = __ldg((const int4*)(ei + N_EDGES) + q);
            g_esrc[atomicAdd(&g_cursor[d4.x], 1)] = s4.x;
            g_esrc[atomicAdd(&g_cursor[d4.y], 1)] = s4.y;
            g_esrc[atomicAdd(&g_cursor[d4.z], 1)] = s4.z;
            g_esrc[atomicAdd(&g_cursor[d4.w], 1)] = s4.w;
        }
    }
}

// ---------------- fp16 chunk accumulate --------------------------------------
__device__ __forceinline__ void acc_chunk(float* a, uint4 q) {
    const __half2* hp = (const __half2*)&q;
#pragma unroll
    for (int j = 0; j < 4; j++) {
        float2 f = __half22float2(hp[j]);
        a[2 * j]     += f.x;
        a[2 * j + 1] += f.y;
    }
}

// ------ agg1: a1h[i] = fp16( relu( dinv[i]*(hs1[i] + sum hs1[src]) + b1 ) ) --
// R12-proven loop: scalar edge loads, 4-deep gather pipeline.
__global__ __launch_bounds__(288) void k_agg1(const float* __restrict__ b1) {
    int t  = threadIdx.x;
    int ln = t / 9;
    int c  = t - ln * 9;
    int i  = blockIdx.x * 32 + ln;
    if (i >= N_NODES) return;

    const uint4* hs = (const uint4*)g_h1h;      // N x 9 chunks
    int beg = __ldg(&g_rowptr[i]);
    int end = __ldg(&g_rowptr[i + 1]);

    float a[8] = {0, 0, 0, 0, 0, 0, 0, 0};
    acc_chunk(a, __ldg(&hs[(unsigned)i * 9 + c]));      // self loop

    int k = beg;
    for (; k + 3 < end; k += 4) {
        int s0 = __ldg(&g_esrc[k]);
        int s1 = __ldg(&g_esrc[k + 1]);
        int s2 = __ldg(&g_esrc[k + 2]);
        int s3 = __ldg(&g_esrc[k + 3]);
        uint4 q0 = __ldg(&hs[(unsigned)s0 * 9 + c]);
        uint4 q1 = __ldg(&hs[(unsigned)s1 * 9 + c]);
        uint4 q2 = __ldg(&hs[(unsigned)s2 * 9 + c]);
        uint4 q3 = __ldg(&hs[(unsigned)s3 * 9 + c]);
        acc_chunk(a, q0); acc_chunk(a, q1); acc_chunk(a, q2); acc_chunk(a, q3);
    }
    for (; k < end; k++) {
        int s = __ldg(&g_esrc[k]);
        acc_chunk(a, __ldg(&hs[(unsigned)s * 9 + c]));
    }

    float d = __ldg(&g_dinv[i]);
    uint4 u;
    __half2* hp = (__half2*)&u;
#pragma unroll
    for (int j = 0; j < 4; j++) {
        int col = 8 * c + 2 * j;
        float bv0 = (col     < D_H1) ? __ldg(b1 + col)     : 0.0f;
        float bv1 = (col + 1 < D_H1) ? __ldg(b1 + col + 1) : 0.0f;
        float v0 = fmaxf(d * a[2 * j]     + bv0, 0.0f);
        float v1 = fmaxf(d * a[2 * j + 1] + bv1, 0.0f);
        hp[j] = __floats2half2_rn(v0, v1);
    }
    g_a1h[(unsigned)i * 9 + c] = u;
}

// ---------------- GEMM2 (tensor core): hs2 = (a1h @ W2) * dinv -> fp16 ------
#define XS2_STRIDE 41   // half2 words per row (40 data + 1 pad, odd stride)
__global__ __launch_bounds__(256) void k_gemm2(const float* __restrict__ W2) {
    __shared__ __half2 Xs[128 * XS2_STRIDE]; // 21.0 KB
    __shared__ __half2 Wsm[40 * 72];         // 11.5 KB
    int t = threadIdx.x;
    int rbase = blockIdx.x * 128;

    // W staging incremental (256 = 3*72+40)
    {
        int kp = t / 72, n = t - kp * 72;
        for (int idx = t; idx < 40 * 72; idx += 256) {
            int k0 = 2 * kp;
            float lo = (k0 < D_H1 && n < D_H2) ? W2[k0 * D_H2 + n] : 0.0f;
            float hi = (k0 + 1 < D_H1 && n < D_H2) ? W2[(k0 + 1) * D_H2 + n] : 0.0f;
            Wsm[kp * 72 + n] = __floats2half2_rn(lo, hi);
            kp += 3; n += 40;
            if (n >= 72) { n -= 72; kp += 1; }
        }
    }

    // X staging incremental (256 = 6*40+16)
    {
        const __half2* a1 = (const __half2*)g_a1h;   // row stride 36 half2
        int rr = t / 40, kp = t - rr * 40;
        for (int idx = t; idx < 128 * 40; idx += 256) {
            int row = rbase + rr;
            __half2 v = __floats2half2_rn(0.0f, 0.0f);
            if (row < N_NODES && kp < 36) v = a1[(unsigned)row * 36 + kp];
            Xs[rr * XS2_STRIDE + kp] = v;
            rr += 6; kp += 16;
            if (kp >= 40) { kp -= 40; rr += 1; }
        }
    }
    __syncthreads();

    int w    = t >> 5;
    int lane = t & 31;
    int g    = lane >> 2;
    int tig  = lane & 3;
    int m0   = w * 16;

    float acc[8][4];
#pragma unroll
    for (int nt = 0; nt < 8; nt++)
#pragma unroll
        for (int j = 0; j < 4; j++) acc[nt][j] = 0.0f;

    const unsigned* XsU = (const unsigned*)Xs;
    const unsigned* WsU = (const unsigned*)Wsm;

#pragma unroll
    for (int ks = 0; ks < 5; ks++) {
        int kb = ks * 8;
        unsigned a0 = XsU[(m0 + g)     * XS2_STRIDE + kb + tig];
        unsigned a1r= XsU[(m0 + g + 8) * XS2_STRIDE + kb + tig];
        unsigned a2 = XsU[(m0 + g)     * XS2_STRIDE + kb + 4 + tig];
        unsigned a3 = XsU[(m0 + g + 8) * XS2_STRIDE + kb + 4 + tig];
#pragma unroll
        for (int nt = 0; nt < 8; nt++) {
            unsigned b0 = WsU[(kb + tig)     * 72 + nt * 8 + g];
            unsigned b1 = WsU[(kb + 4 + tig) * 72 + nt * 8 + g];
            asm volatile(
                "mma.sync.aligned.m16n8k16.row.col.f32.f16.f16.f32 "
                "{%0,%1,%2,%3}, {%4,%5,%6,%7}, {%8,%9}, {%0,%1,%2,%3};"
                : "+f"(acc[nt][0]), "+f"(acc[nt][1]),
                  "+f"(acc[nt][2]), "+f"(acc[nt][3])
                : "r"(a0), "r"(a1r), "r"(a2), "r"(a3), "r"(b0), "r"(b1));
        }
    }

    __half2* h2out = (__half2*)g_h2h;          // row stride 32 half2
    int row0 = rbase + m0 + g;
    int row1 = row0 + 8;
    float d0 = (row0 < N_NODES) ? g_dinv[row0] : 0.0f;
    float d1 = (row1 < N_NODES) ? g_dinv[row1] : 0.0f;
#pragma unroll
    for (int nt = 0; nt < 8; nt++) {
        int cw = nt * 4 + tig;
        if (row0 < N_NODES)
            h2out[(unsigned)row0 * 32 + cw] =
                __floats2half2_rn(acc[nt][0] * d0, acc[nt][1] * d0);
        if (row1 < N_NODES)
            h2out[(unsigned)row1 * 32 + cw] =
                __floats2half2_rn(acc[nt][2] * d1, acc[nt][3] * d1);
    }
}

// ------- agg2 + output fused: out[i]=relu(sum_c relu(agg2_c+b2)*Wout + bout) -
// R12-proven loop: scalar edge loads, 4-deep gather pipeline.
__global__ __launch_bounds__(256) void k_agg2out(const float* __restrict__ b2,
                                                 const float* __restrict__ Wout,
                                                 const float* __restrict__ bout,
                                                 float* __restrict__ out) {
    int t  = threadIdx.x;
    int ln = t >> 3;
    int c  = t & 7;
    int i  = blockIdx.x * 32 + ln;
    if (i >= N_NODES) return;

    const uint4* hs = (const uint4*)g_h2h;      // N x 8 chunks
    int beg = __ldg(&g_rowptr[i]);
    int end = __ldg(&g_rowptr[i + 1]);

    float a[8] = {0, 0, 0, 0, 0, 0, 0, 0};
    acc_chunk(a, __ldg(&hs[(unsigned)i * 8 + c]));      // self loop

    int k = beg;
    for (; k + 3 < end; k += 4) {
        int s0 = __ldg(&g_esrc[k]);
        int s1 = __ldg(&g_esrc[k + 1]);
        int s2 = __ldg(&g_esrc[k + 2]);
        int s3 = __ldg(&g_esrc[k + 3]);
        uint4 q0 = __ldg(&hs[(unsigned)s0 * 8 + c]);
        uint4 q1 = __ldg(&hs[(unsigned)s1 * 8 + c]);
        uint4 q2 = __ldg(&hs[(unsigned)s2 * 8 + c]);
        uint4 q3 = __ldg(&hs[(unsigned)s3 * 8 + c]);
        acc_chunk(a, q0); acc_chunk(a, q1); acc_chunk(a, q2); acc_chunk(a, q3);
    }
    for (; k < end; k++) {
        int s = __ldg(&g_esrc[k]);
        acc_chunk(a, __ldg(&hs[(unsigned)s * 8 + c]));
    }

    float d = __ldg(&g_dinv[i]);
    float4 b2a = __ldg((const float4*)b2 + c * 2);
    float4 b2b = __ldg((const float4*)b2 + c * 2 + 1);
    float4 woa = __ldg((const float4*)Wout + c * 2);
    float4 wob = __ldg((const float4*)Wout + c * 2 + 1);

    float s = fmaxf(d * a[0] + b2a.x, 0.0f) * woa.x
            + fmaxf(d * a[1] + b2a.y, 0.0f) * woa.y
            + fmaxf(d * a[2] + b2a.z, 0.0f) * woa.z
            + fmaxf(d * a[3] + b2a.w, 0.0f) * woa.w
            + fmaxf(d * a[4] + b2b.x, 0.0f) * wob.x
            + fmaxf(d * a[5] + b2b.y, 0.0f) * wob.y
            + fmaxf(d * a[6] + b2b.z, 0.0f) * wob.z
            + fmaxf(d * a[7] + b2b.w, 0.0f) * wob.w;

    s += __shfl_xor_sync(0xffffffffu, s, 1);
    s += __shfl_xor_sync(0xffffffffu, s, 2);
    s += __shfl_xor_sync(0xffffffffu, s, 4);
    if (c == 0) out[i] = fmaxf(s + __ldg(bout), 0.0f);
}

// ---------------- launch ----------------------------------------------------
extern "C" void kernel_launch(void* const* d_in, const int* in_sizes, int n_in,
                              void* d_out, int out_size) {
    const float* x    = (const float*)d_in[0];
    const int*   ei   = (const int*)  d_in[1];
    const float* W1   = (const float*)d_in[2];
    const float* b1   = (const float*)d_in[3];
    const float* W2   = (const float*)d_in[4];
    const float* b2   = (const float*)d_in[5];
    const float* Wout = (const float*)d_in[6];
    const float* bout = (const float*)d_in[7];
    float* out = (float*)d_out;

    const int NB_N = (N_NODES + 255) / 256;
    const int NB_E4 = (N_EDGES / 4 + 255) / 256;   // int4 deg_count
    const int NB_G = (N_NODES + 127) / 128;        // 1563 blocks, 128 rows each
    const int NB_A = (N_NODES + 31) / 32;          // 6250

    k_deg_zero <<<NB_N, 256>>>();
    k_deg_count<<<NB_E4, 256>>>(ei);
    k_scan1    <<<SCAN_NB, SCAN_B>>>();       // also computes dinv
    k_scan2    <<<1, 256>>>();
    k_scan3    <<<SCAN_NB, SCAN_B>>>();
    k_gemm1    <<<NB_G, 256>>>(x, W1, ei);    // MMA + fused CSR scatter
    k_agg1     <<<NB_A, 288>>>(b1);
    k_gemm2    <<<NB_G, 256>>>(W2);
    k_agg2out  <<<NB_A, 256>>>(b2, Wout, bout, out);
}